// round 14
// baseline (speedup 1.0000x reference)
#include <cuda_runtime.h>
#include <cuda_bf16.h>
#include <math.h>
#include <stdint.h>

// ---------------------------------------------------------------------------
// AdaptiveLogSoftmax NLL — bounded-concurrency schedule.
//  s1:      prep -> wconv(104 CTAs, runs on SMs proj leaves idle)
//  stream0: proj(88 CTAs) -> [wait wconv] -> merged fp8 launch -> combine
// Merged launch: 64 gather CTAs + head + tail1 + tail3 + tail2 GEMMs
// (m16n8k32 e4m3, 3-stage cp.async pipeline, exp2 epilogue) — unchanged.
// ---------------------------------------------------------------------------

#define NROWS 1024
#define HEAD_SIZE 20003
#define PCW 1360
#define PCWP 1408
#define LOG2E 1.4426950408889634f
#define INV64_LOG2E (LOG2E / 64.f)
#define GATHER_CTAS 64
#define WCONV_CTAS 104

__device__ __align__(16) float    g_proj[NROWS * PCW];
__device__ __align__(16) uint8_t  g_proj8[NROWS * PCWP];
__device__ __align__(16) uint8_t  g_w0b[20003 * 1024];
__device__ __align__(16) uint8_t  g_w1b[20000 * 256];
__device__ __align__(16) uint8_t  g_w2b[160000 * 64];
__device__ __align__(16) uint8_t  g_w3b[67735 * 64];
__device__ float g_S0[NROWS];
__device__ float g_St[NROWS];
__device__ float g_ghead[NROWS];
__device__ float g_gtail[NROWS];
__device__ int   g_rowlist[3 * NROWS];
__device__ int   g_count[3];
__device__ int   g_cluster[NROWS];

// ---------------- helpers ---------------------------------------------------
__device__ __forceinline__ uint32_t f2tf(float f) {
    uint32_t r;
    asm("cvt.rna.tf32.f32 %0, %1;" : "=r"(r) : "f"(f));
    return r;
}
__device__ __forceinline__ uint16_t pack_e4m3(float lo, float hi) {
    uint16_t r;
    asm("cvt.rn.satfinite.e4m3x2.f32 %0, %1, %2;" : "=h"(r) : "f"(hi), "f"(lo));
    return r;
}
__device__ __forceinline__ uint32_t pack4_e4m3_x8(float4 v) {
    uint16_t l = pack_e4m3(v.x * 8.f, v.y * 8.f);
    uint16_t h = pack_e4m3(v.z * 8.f, v.w * 8.f);
    return (uint32_t)l | ((uint32_t)h << 16);
}

#define MMA_TF32(c, a, b)                                                     \
    asm volatile(                                                             \
        "mma.sync.aligned.m16n8k8.row.col.f32.tf32.tf32.f32 "                 \
        "{%0,%1,%2,%3},{%4,%5,%6,%7},{%8,%9},{%0,%1,%2,%3};"                  \
        : "+f"(c[0]), "+f"(c[1]), "+f"(c[2]), "+f"(c[3])                      \
        : "r"(a[0]), "r"(a[1]), "r"(a[2]), "r"(a[3]), "r"(b[0]), "r"(b[1]))

#define MMA_FP8(c, a0, a1, a2, a3, b0, b1)                                    \
    asm volatile(                                                             \
        "mma.sync.aligned.m16n8k32.row.col.f32.e4m3.e4m3.f32 "                \
        "{%0,%1,%2,%3},{%4,%5,%6,%7},{%8,%9},{%0,%1,%2,%3};"                  \
        : "+f"(c[0]), "+f"(c[1]), "+f"(c[2]), "+f"(c[3])                      \
        : "r"(a0), "r"(a1), "r"(a2), "r"(a3), "r"(b0), "r"(b1))

#define LDSM4(r0, r1, r2, r3, addr)                                           \
    asm volatile("ldmatrix.sync.aligned.m8n8.x4.shared.b16 {%0,%1,%2,%3}, [%4];" \
        : "=r"(r0), "=r"(r1), "=r"(r2), "=r"(r3) : "r"(addr))

#define CP_ASYNC16(smem, gptr)                                                \
    asm volatile("cp.async.cg.shared.global [%0], [%1], 16;"                  \
        :: "r"(smem), "l"(gptr) : "memory")
#define CP_COMMIT()  asm volatile("cp.async.commit_group;" ::: "memory")
#define CP_WAIT(n)   asm volatile("cp.async.wait_group %0;" :: "n"(n) : "memory")

#define LDW 20
#define MATB (128 * LDW * 4)
#define STAGEB (2 * MATB)
#define NSTAGE 3
#define DSMEM (NSTAGE * STAGEB)

// ---------------- merged problem table --------------------------------------
struct SEP {
    const uint8_t* A;
    const uint8_t* B;
    const float*   bias;
    float*         Ssum;
    int Nc, K, nx, base;
    const int* rowmap;
    const int* countPtr;
};
struct MPAR {
    SEP p[4];
    const float *w0, *b0, *w1, *b1, *w2, *b2, *w3, *b3;
    const int* target;
};

// ===========================================================================
// Merged launch: bx < GATHER_CTAS do the exact-gather; the rest run the
// fp8 GEMM + fused sum-exp (3-stage cp.async pipeline).
// ===========================================================================
__global__ void __launch_bounds__(256, 2) fp8_sumexp_multi(MPAR P)
{
    extern __shared__ __align__(16) uint32_t dyn[];
    __shared__ float rsum[128];

    const int bx = blockIdx.x;
    const int tid  = threadIdx.x;
    const int lane = tid & 31;
    const int wid  = tid >> 5;

    if (bx < GATHER_CTAS) {
        for (int t = bx * 8 + wid; t < 2 * NROWS; t += GATHER_CTAS * 8) {
            if (t < NROWS) {
                int row = t;
                int c = g_cluster[row];
                int col = (c == 0) ? P.target[row] : (HEAD_SIZE - c);
                const float4* pr = (const float4*)(g_proj + (size_t)row * PCW);
                const float4* wr = (const float4*)(P.w0 + (size_t)col * 1024);
                float s = 0.f;
                for (int i = lane; i < 256; i += 32) {
                    float4 a = pr[i], b = wr[i];
                    s += a.x * b.x + a.y * b.y + a.z * b.z + a.w * b.w;
                }
#pragma unroll
                for (int o = 16; o; o >>= 1) s += __shfl_down_sync(0xffffffffu, s, o);
                if (lane == 0) g_ghead[row] = s + P.b0[col];
            } else {
                int row = t - NROWS;
                int c = g_cluster[row];
                if (c == 0) continue;
                const float* pr; const float* W; const float* bb; int K, off;
                if (c == 1)      { pr = g_proj + (size_t)row * PCW + 1024; W = P.w1; bb = P.b1; K = 256; off = 20000; }
                else if (c == 2) { pr = g_proj + (size_t)row * PCW + 1280; W = P.w2; bb = P.b2; K = 64;  off = 40000; }
                else             { pr = g_proj + (size_t)row * PCW + 1344; W = P.w3; bb = P.b3; K = 16;  off = 200000; }
                int ti = P.target[row] - off;
                float s = 0.f;
                for (int k = lane; k < K; k += 32) s += pr[k] * W[(size_t)ti * K + k];
#pragma unroll
                for (int o = 16; o; o >>= 1) s += __shfl_down_sync(0xffffffffu, s, o);
                if (lane == 0) g_gtail[row] = s + bb[ti];
            }
        }
        return;
    }

    const int pi = (bx >= P.p[1].base) + (bx >= P.p[2].base) + (bx >= P.p[3].base);
    const SEP sp = P.p[pi];
    const int local = bx - sp.base;
    const int tileX = local % sp.nx;
    const int tileY = local / sp.nx;

    const int count = sp.countPtr ? *sp.countPtr : NROWS;
    const int rowBase = tileY * 128;
    if (rowBase >= count) return;
    const int colBase = tileX * 128;
    const int Nc = sp.Nc, K = sp.K;

    const int mBase = (wid & 1) * 64;
    const int nBase = (wid >> 1) * 32;
    const int lq = lane >> 2;
    const int lr = lane & 3;

    if (tid < 128) rsum[tid] = 0.f;

    const int ar   = tid >> 1;
    const int half = tid & 1;
    const int gA   = rowBase + ar;
    const bool aval = (gA < count);
    const int arow = aval ? (sp.rowmap ? sp.rowmap[gA] : gA) : 0;
    const uint8_t* Ag = sp.A + (size_t)arow * PCWP + half * 32;
    int gB = colBase + ar; if (gB >= Nc) gB = Nc - 1;
    const uint8_t* Bg = sp.B + (size_t)gB * K + half * 32;

    const uint32_t smb = (uint32_t)__cvta_generic_to_shared(dyn);
    const uint32_t aSlot = smb + (ar * LDW + half * 8) * 4;
    const uint32_t bSlot = smb + MATB + (ar * LDW + half * 8) * 4;
    const uint32_t aFrag = smb + ((mBase + (lane & 15)) * LDW + (lane >> 4) * 4) * 4;
    const uint32_t bFrag = smb + MATB + ((nBase + lane) * LDW) * 4;

    float acc[4][4][4];
#pragma unroll
    for (int i = 0; i < 4; i++)
#pragma unroll
        for (int j = 0; j < 4; j++)
#pragma unroll
            for (int r = 0; r < 4; r++) acc[i][j][r] = 0.f;

    const int nch = K >> 6;

    CP_ASYNC16(aSlot, Ag);          CP_ASYNC16(aSlot + 16, Ag + 16);
    CP_ASYNC16(bSlot, Bg);          CP_ASYNC16(bSlot + 16, Bg + 16);
    CP_COMMIT();
    if (nch > 1) {
        CP_ASYNC16(aSlot + STAGEB, Ag + 64);      CP_ASYNC16(aSlot + STAGEB + 16, Ag + 80);
        CP_ASYNC16(bSlot + STAGEB, Bg + 64);      CP_ASYNC16(bSlot + STAGEB + 16, Bg + 80);
        CP_COMMIT();
    }

    int buf = 0;
    for (int c = 0; c < nch; ++c) {
        if (c + 1 < nch) CP_WAIT(1); else CP_WAIT(0);
        __syncthreads();

        if (c + 2 < nch) {
            int nb = buf + 2; if (nb >= NSTAGE) nb -= NSTAGE;
            const uint32_t off = nb * STAGEB;
            const uint8_t* an = Ag + ((c + 2) << 6);
            const uint8_t* bn = Bg + ((c + 2) << 6);
            CP_ASYNC16(aSlot + off, an); CP_ASYNC16(aSlot + off + 16, an + 16);
            CP_ASYNC16(bSlot + off, bn); CP_ASYNC16(bSlot + off + 16, bn + 16);
            CP_COMMIT();
        }

        const uint32_t aB = aFrag + buf * STAGEB;
        const uint32_t bB = bFrag + buf * STAGEB;
#pragma unroll
        for (int cc = 0; cc < 2; ++cc) {
            uint32_t af[4][4], b0r[4], b1r[4];
            LDSM4(b0r[0], b0r[1], b0r[2], b0r[3], bB + cc * 32);
            LDSM4(b1r[0], b1r[1], b1r[2], b1r[3], bB + cc * 32 + 16);
#pragma unroll
            for (int mt = 0; mt < 4; mt++)
                LDSM4(af[mt][0], af[mt][1], af[mt][2], af[mt][3],
                      aB + mt * (16 * LDW * 4) + cc * 32);
#pragma unroll
            for (int mt = 0; mt < 4; mt++)
#pragma unroll
                for (int nt = 0; nt < 4; nt++)
                    MMA_FP8(acc[mt][nt],
                            af[mt][0], af[mt][1], af[mt][2], af[mt][3],
                            b0r[nt], b1r[nt]);
        }

        if (++buf == NSTAGE) buf = 0;
    }

    float rs[4][2];
#pragma unroll
    for (int mt = 0; mt < 4; mt++) { rs[mt][0] = 0.f; rs[mt][1] = 0.f; }

    const float* bptr = sp.bias + colBase + nBase;
    if (colBase + 128 <= Nc) {
#pragma unroll
        for (int nt = 0; nt < 4; nt++) {
            int cc0 = nt * 8 + 2 * lr;
            float bv0 = bptr[cc0] * LOG2E;
            float bv1 = bptr[cc0 + 1] * LOG2E;
#pragma unroll
            for (int mt = 0; mt < 4; mt++) {
                rs[mt][0] += exp2f(fmaf(acc[mt][nt][0], INV64_LOG2E, bv0));
                rs[mt][1] += exp2f(fmaf(acc[mt][nt][2], INV64_LOG2E, bv0));
                rs[mt][0] += exp2f(fmaf(acc[mt][nt][1], INV64_LOG2E, bv1));
                rs[mt][1] += exp2f(fmaf(acc[mt][nt][3], INV64_LOG2E, bv1));
            }
        }
    } else {
#pragma unroll
        for (int nt = 0; nt < 4; nt++) {
            int gc = colBase + nBase + nt * 8 + 2 * lr;
            bool v0 = gc < Nc, v1 = (gc + 1) < Nc;
            float bv0 = v0 ? sp.bias[gc] * LOG2E : 0.f;
            float bv1 = v1 ? sp.bias[gc + 1] * LOG2E : 0.f;
#pragma unroll
            for (int mt = 0; mt < 4; mt++) {
                if (v0) {
                    rs[mt][0] += exp2f(fmaf(acc[mt][nt][0], INV64_LOG2E, bv0));
                    rs[mt][1] += exp2f(fmaf(acc[mt][nt][2], INV64_LOG2E, bv0));
                }
                if (v1) {
                    rs[mt][0] += exp2f(fmaf(acc[mt][nt][1], INV64_LOG2E, bv1));
                    rs[mt][1] += exp2f(fmaf(acc[mt][nt][3], INV64_LOG2E, bv1));
                }
            }
        }
    }
#pragma unroll
    for (int mt = 0; mt < 4; mt++)
#pragma unroll
        for (int h = 0; h < 2; h++) {
            float v = rs[mt][h];
            v += __shfl_xor_sync(0xffffffffu, v, 1);
            v += __shfl_xor_sync(0xffffffffu, v, 2);
            if (lr == 0)
                atomicAdd(&rsum[mBase + mt * 16 + h * 8 + lq], v);
        }
    __syncthreads();
    if (tid < 128) {
        int gr = rowBase + tid;
        if (gr < count) {
            int n = sp.rowmap ? sp.rowmap[gr] : gr;
            atomicAdd(&sp.Ssum[n], rsum[tid]);
        }
    }
}

// ===========================================================================
// tf32 proj GEMM: proj = hidden @ [p0|p1|p2|p3] directly (no concat).
// ===========================================================================
__global__ void __launch_bounds__(256, 2) proj_gemm(
    const float* __restrict__ A,
    const float* __restrict__ p0, const float* __restrict__ p1,
    const float* __restrict__ p2, const float* __restrict__ p3,
    float* __restrict__ C, uint8_t* __restrict__ C8)
{
    const int Nc = PCW, K = 1024;
    __shared__ uint32_t As[128 * LDW];
    __shared__ uint32_t Bs[128 * LDW];

    const int rowBase = blockIdx.y * 128;
    const int colBase = blockIdx.x * 128;

    const int tid  = threadIdx.x;
    const int lane = tid & 31;
    const int wid  = tid >> 5;
    const int mBase = (wid & 1) * 64;
    const int nBase = (wid >> 1) * 32;
    const int lq = lane >> 2;
    const int lr = lane & 3;

    const int ar  = tid >> 1;
    const int akk = (tid & 1) * 8;
    const float* Aptr = A + (size_t)(rowBase + ar) * K + akk;

    const int bkk = tid >> 4;
    const int br  = (tid & 15) * 8;
    const int gc  = colBase + br;
    const bool bval = gc < Nc;
    const float* src; int snc, scol;
    if (gc < 1024)      { src = p0; snc = 1024; scol = gc; }
    else if (gc < 1280) { src = p1; snc = 256;  scol = gc - 1024; }
    else if (gc < 1344) { src = p2; snc = 64;   scol = gc - 1280; }
    else                { src = p3; snc = 16;   scol = bval ? gc - 1344 : 0; }
    const float* Bptr = src + scol;

    const float4 fz = make_float4(0.f, 0.f, 0.f, 0.f);
    float4 aR0, aR1, bR0, bR1;
    aR0 = *(const float4*)(Aptr);
    aR1 = *(const float4*)(Aptr + 4);
    bR0 = bval ? *(const float4*)(Bptr + (size_t)bkk * snc)     : fz;
    bR1 = bval ? *(const float4*)(Bptr + (size_t)bkk * snc + 4) : fz;

    float acc[4][4][4];
#pragma unroll
    for (int i = 0; i < 4; i++)
#pragma unroll
        for (int j = 0; j < 4; j++)
#pragma unroll
            for (int r = 0; r < 4; r++) acc[i][j][r] = 0.f;

    for (int k0 = 0; k0 < K; k0 += 16) {
        {
            uint32_t* ap = &As[ar * LDW + akk];
            ap[0] = f2tf(aR0.x); ap[1] = f2tf(aR0.y); ap[2] = f2tf(aR0.z); ap[3] = f2tf(aR0.w);
            ap[4] = f2tf(aR1.x); ap[5] = f2tf(aR1.y); ap[6] = f2tf(aR1.z); ap[7] = f2tf(aR1.w);
            float v[8] = {bR0.x, bR0.y, bR0.z, bR0.w, bR1.x, bR1.y, bR1.z, bR1.w};
#pragma unroll
            for (int q = 0; q < 8; q++) Bs[(br + q) * LDW + bkk] = f2tf(v[q]);
        }
        __syncthreads();

        const int kn = k0 + 16;
        if (kn < K) {
            aR0 = *(const float4*)(Aptr + kn);
            aR1 = *(const float4*)(Aptr + kn + 4);
            bR0 = bval ? *(const float4*)(Bptr + (size_t)(kn + bkk) * snc)     : fz;
            bR1 = bval ? *(const float4*)(Bptr + (size_t)(kn + bkk) * snc + 4) : fz;
        }

#pragma unroll
        for (int ks = 0; ks < 16; ks += 8) {
            uint32_t af[4][4], bf[4][2];
#pragma unroll
            for (int mt = 0; mt < 4; mt++) {
                int r = mBase + mt * 16 + lq;
                int c = ks + lr;
                af[mt][0] = As[r * LDW + c];
                af[mt][1] = As[(r + 8) * LDW + c];
                af[mt][2] = As[r * LDW + c + 4];
                af[mt][3] = As[(r + 8) * LDW + c + 4];
            }
#pragma unroll
            for (int nt = 0; nt < 4; nt++) {
                int n = nBase + nt * 8 + lq;
                bf[nt][0] = Bs[n * LDW + ks + lr];
                bf[nt][1] = Bs[n * LDW + ks + 4 + lr];
            }
#pragma unroll
            for (int mt = 0; mt < 4; mt++)
#pragma unroll
                for (int nt = 0; nt < 4; nt++)
                    MMA_TF32(acc[mt][nt], af[mt], bf[nt]);
        }
        __syncthreads();
    }

#pragma unroll
    for (int mt = 0; mt < 4; mt++) {
        int r0 = rowBase + mBase + mt * 16 + lq;
#pragma unroll
        for (int nt = 0; nt < 4; nt++) {
            int c2 = colBase + nBase + nt * 8 + 2 * lr;
            if (c2 < Nc) {
                float* q0 = C + (size_t)r0 * Nc + c2;
                float* q1 = C + (size_t)(r0 + 8) * Nc + c2;
                q0[0] = acc[mt][nt][0]; q0[1] = acc[mt][nt][1];
                q1[0] = acc[mt][nt][2]; q1[1] = acc[mt][nt][3];
                ((uint16_t*)C8)[((size_t)r0 * PCWP + c2) >> 1] =
                    pack_e4m3(acc[mt][nt][0] * 8.f, acc[mt][nt][1] * 8.f);
                ((uint16_t*)C8)[((size_t)(r0 + 8) * PCWP + c2) >> 1] =
                    pack_e4m3(acc[mt][nt][2] * 8.f, acc[mt][nt][3] * 8.f);
            }
        }
    }
}

// ---------------- prep / wconv / combine ------------------------------------
__global__ void prep_kernel(const int* __restrict__ target) {
    int i = threadIdx.x;
    g_S0[i] = 0.f; g_St[i] = 0.f;
    if (i < 3) g_count[i] = 0;
    __syncthreads();
    int t = target[i];
    int c = (t < 20000) ? 0 : (t < 40000) ? 1 : (t < 200000) ? 2 : 3;
    g_cluster[i] = c;
    if (c > 0) {
        int idx = atomicAdd(&g_count[c - 1], 1);
        g_rowlist[(c - 1) * NROWS + idx] = i;
    }
}

__global__ void wconv_kernel(
    const float4* __restrict__ w0, const float4* __restrict__ w1,
    const float4* __restrict__ w2, const float4* __restrict__ w3)
{
    const int T1 = 5120768;           // w0: 20003*1024/4
    const int T2 = T1 + 1280000;      // w1: 20000*256/4
    const int T3 = T2 + 2560000;      // w2: 160000*64/4
    const int T4 = T3 + 270940;       // w3 data: 67735*16/4
    const int T5 = T4 + 812820;       // w3 pad zeros: 67735*12
    const int T6 = T5 + 12288;        // proj8 pad zeros: 1024*12
    for (int i = blockIdx.x * blockDim.x + threadIdx.x; i < T6;
         i += gridDim.x * blockDim.x) {
        if (i < T1) {
            ((uint32_t*)g_w0b)[i] = pack4_e4m3_x8(w0[i]);
        } else if (i < T2) {
            int j = i - T1;
            ((uint32_t*)g_w1b)[j] = pack4_e4m3_x8(w1[j]);
        } else if (i < T3) {
            int j = i - T2;
            ((uint32_t*)g_w2b)[j] = pack4_e4m3_x8(w2[j]);
        } else if (i < T4) {
            int j = i - T3;
            int row = j >> 2, q = j & 3;
            ((uint32_t*)g_w3b)[row * 16 + q] = pack4_e4m3_x8(w3[j]);
        } else if (i < T5) {
            int j = i - T4;
            int row = j / 12, word = j - row * 12;
            ((uint32_t*)g_w3b)[row * 16 + 4 + word] = 0u;
        } else {
            int j = i - T5;
            int row = j / 12, word = j - row * 12;
            ((uint32_t*)g_proj8)[row * 352 + 340 + word] = 0u;
        }
    }
}

__global__ void combine_kernel(float* __restrict__ out, int n) {
    int i = blockIdx.x * blockDim.x + threadIdx.x;
    if (i >= n) return;
    float v = logf(g_S0[i]) - g_ghead[i];
    if (g_cluster[i] > 0) v += logf(g_St[i]) - g_gtail[i];
    out[i] = v;
}

// ---------------- launch ----------------------------------------------------
extern "C" void kernel_launch(void* const* d_in, const int* in_sizes, int n_in,
                              void* d_out, int out_size) {
    const float* hidden = (const float*)d_in[0];
    const int*   target = (const int*)d_in[1];
    const float* w0 = (const float*)d_in[2];
    const float* b0 = (const float*)d_in[3];
    const float* p0 = (const float*)d_in[4];
    const float* w1 = (const float*)d_in[5];
    const float* b1 = (const float*)d_in[6];
    const float* p1 = (const float*)d_in[7];
    const float* w2 = (const float*)d_in[8];
    const float* b2 = (const float*)d_in[9];
    const float* p2 = (const float*)d_in[10];
    const float* w3 = (const float*)d_in[11];
    const float* b3 = (const float*)d_in[12];
    const float* p3 = (const float*)d_in[13];
    float* out = (float*)d_out;

    float *proj, *S0, *St;
    uint8_t *proj8, *w0b, *w1b, *w2b, *w3b;
    int *rowlist, *cnt;
    cudaGetSymbolAddress((void**)&proj, g_proj);
    cudaGetSymbolAddress((void**)&proj8, g_proj8);
    cudaGetSymbolAddress((void**)&w0b, g_w0b);
    cudaGetSymbolAddress((void**)&w1b, g_w1b);
    cudaGetSymbolAddress((void**)&w2b, g_w2b);
    cudaGetSymbolAddress((void**)&w3b, g_w3b);
    cudaGetSymbolAddress((void**)&S0, g_S0);
    cudaGetSymbolAddress((void**)&St, g_St);
    cudaGetSymbolAddress((void**)&rowlist, g_rowlist);
    cudaGetSymbolAddress((void**)&cnt, g_count);

    const int N = NROWS;

    static bool initDone = false;
    static cudaStream_t s1;
    static cudaEvent_t evRoot, evW;
    if (!initDone) {
        cudaFuncSetAttribute(fp8_sumexp_multi,
                             cudaFuncAttributeMaxDynamicSharedMemorySize, DSMEM);
        cudaStreamCreateWithFlags(&s1, cudaStreamNonBlocking);
        cudaEventCreateWithFlags(&evRoot, cudaEventDisableTiming);
        cudaEventCreateWithFlags(&evW, cudaEventDisableTiming);
        initDone = true;
    }

    // fork: s1 runs prep + wconv on SMs proj leaves idle (proj uses 44 SMs)
    cudaEventRecord(evRoot, 0);
    cudaStreamWaitEvent(s1, evRoot, 0);
    prep_kernel<<<1, 1024, 0, s1>>>(target);
    wconv_kernel<<<WCONV_CTAS, 256, 0, s1>>>(
        (const float4*)w0, (const float4*)w1,
        (const float4*)w2, (const float4*)w3);
    cudaEventRecord(evW, s1);

    // stream 0: proj (88 CTAs), concurrent with wconv
    proj_gemm<<<dim3(11, 8, 1), 256>>>(hidden, p0, p1, p2, p3, proj, proj8);

    // join, then merged launch + combine on stream 0
    cudaStreamWaitEvent(0, evW, 0);
    MPAR P;
    P.p[0] = { proj8,        w0b, b0, S0, HEAD_SIZE, 1024, 157,
               GATHER_CTAS, nullptr, nullptr };                      // 1256
    P.p[1] = { proj8 + 1024, w1b, b1, St, 20000, 256, 157,
               GATHER_CTAS + 1256, rowlist + 0 * NROWS, cnt + 0 };   // 1256
    P.p[2] = { proj8 + 1344, w3b, b3, St, 67735, 64, 530,
               GATHER_CTAS + 2512, rowlist + 2 * NROWS, cnt + 2 };   // 4240
    P.p[3] = { proj8 + 1280, w2b, b2, St, 160000, 64, 1250,
               GATHER_CTAS + 6752, rowlist + 1 * NROWS, cnt + 1 };   // 10000
    P.w0 = w0; P.b0 = b0; P.w1 = w1; P.b1 = b1;
    P.w2 = w2; P.b2 = b2; P.w3 = w3; P.b3 = b3;
    P.target = target;
    fp8_sumexp_multi<<<GATHER_CTAS + 16752, 256, DSMEM>>>(P);

    combine_kernel<<<(N + 255) / 256, 256>>>(out, N);
}

// round 15
// speedup vs baseline: 1.0694x; 1.0694x over previous
#include <cuda_runtime.h>
#include <cuda_bf16.h>
#include <math.h>
#include <stdint.h>

// ---------------------------------------------------------------------------
// AdaptiveLogSoftmax NLL — single stream, 3 launches.
//   wconv+prep: CTA0 classifies rows; all CTAs convert weights -> e4m3 (x8)
//   proj:       proj = hidden @ [p0|p1|p2|p3] (tf32, direct B, no concat)
//   merged:     64 gather CTAs + head/tail1/tail3/tail2 fp8 sum-exp GEMMs;
//               last CTA (fence+counter) computes the final NLL output.
// ---------------------------------------------------------------------------

#define NROWS 1024
#define HEAD_SIZE 20003
#define PCW 1360
#define PCWP 1408
#define LOG2E 1.4426950408889634f
#define INV64_LOG2E (LOG2E / 64.f)
#define GATHER_CTAS 64

__device__ __align__(16) float    g_proj[NROWS * PCW];
__device__ __align__(16) uint8_t  g_proj8[NROWS * PCWP];
__device__ __align__(16) uint8_t  g_w0b[20003 * 1024];
__device__ __align__(16) uint8_t  g_w1b[20000 * 256];
__device__ __align__(16) uint8_t  g_w2b[160000 * 64];
__device__ __align__(16) uint8_t  g_w3b[67735 * 64];
__device__ float g_S0[NROWS];
__device__ float g_St[NROWS];
__device__ float g_ghead[NROWS];
__device__ float g_gtail[NROWS];
__device__ int   g_rowlist[3 * NROWS];
__device__ int   g_count[3];
__device__ int   g_cluster[NROWS];
__device__ int   g_done;

// ---------------- helpers ---------------------------------------------------
__device__ __forceinline__ uint32_t f2tf(float f) {
    uint32_t r;
    asm("cvt.rna.tf32.f32 %0, %1;" : "=r"(r) : "f"(f));
    return r;
}
__device__ __forceinline__ uint16_t pack_e4m3(float lo, float hi) {
    uint16_t r;
    asm("cvt.rn.satfinite.e4m3x2.f32 %0, %1, %2;" : "=h"(r) : "f"(hi), "f"(lo));
    return r;
}
__device__ __forceinline__ uint32_t pack4_e4m3_x8(float4 v) {
    uint16_t l = pack_e4m3(v.x * 8.f, v.y * 8.f);
    uint16_t h = pack_e4m3(v.z * 8.f, v.w * 8.f);
    return (uint32_t)l | ((uint32_t)h << 16);
}

#define MMA_TF32(c, a, b)                                                     \
    asm volatile(                                                             \
        "mma.sync.aligned.m16n8k8.row.col.f32.tf32.tf32.f32 "                 \
        "{%0,%1,%2,%3},{%4,%5,%6,%7},{%8,%9},{%0,%1,%2,%3};"                  \
        : "+f"(c[0]), "+f"(c[1]), "+f"(c[2]), "+f"(c[3])                      \
        : "r"(a[0]), "r"(a[1]), "r"(a[2]), "r"(a[3]), "r"(b[0]), "r"(b[1]))

#define MMA_FP8(c, a0, a1, a2, a3, b0, b1)                                    \
    asm volatile(                                                             \
        "mma.sync.aligned.m16n8k32.row.col.f32.e4m3.e4m3.f32 "                \
        "{%0,%1,%2,%3},{%4,%5,%6,%7},{%8,%9},{%0,%1,%2,%3};"                  \
        : "+f"(c[0]), "+f"(c[1]), "+f"(c[2]), "+f"(c[3])                      \
        : "r"(a0), "r"(a1), "r"(a2), "r"(a3), "r"(b0), "r"(b1))

#define LDSM4(r0, r1, r2, r3, addr)                                           \
    asm volatile("ldmatrix.sync.aligned.m8n8.x4.shared.b16 {%0,%1,%2,%3}, [%4];" \
        : "=r"(r0), "=r"(r1), "=r"(r2), "=r"(r3) : "r"(addr))

#define CP_ASYNC16(smem, gptr)                                                \
    asm volatile("cp.async.cg.shared.global [%0], [%1], 16;"                  \
        :: "r"(smem), "l"(gptr) : "memory")
#define CP_COMMIT()  asm volatile("cp.async.commit_group;" ::: "memory")
#define CP_WAIT(n)   asm volatile("cp.async.wait_group %0;" :: "n"(n) : "memory")

#define LDW 20
#define MATB (128 * LDW * 4)
#define STAGEB (2 * MATB)
#define NSTAGE 3
#define DSMEM (NSTAGE * STAGEB)

// ---------------- merged problem table --------------------------------------
struct SEP {
    const uint8_t* A;
    const uint8_t* B;
    const float*   bias;
    float*         Ssum;
    int Nc, K, nx, base;
    const int* rowmap;
    const int* countPtr;
};
struct MPAR {
    SEP p[4];
    const float *w0, *b0, *w1, *b1, *w2, *b2, *w3, *b3;
    const int* target;
    float* out;
};

// Last-CTA combine: every CTA calls this exactly once at its end.
__device__ __forceinline__ void cta_finish(float* __restrict__ out) {
    __shared__ int isLast;
    __threadfence();
    __syncthreads();
    if (threadIdx.x == 0) {
        int v = atomicAdd(&g_done, 1);
        isLast = (v == (int)gridDim.x - 1);
    }
    __syncthreads();
    if (isLast) {
        __threadfence();
        for (int i = threadIdx.x; i < NROWS; i += blockDim.x) {
            float v = logf(g_S0[i]) - g_ghead[i];
            if (g_cluster[i] > 0) v += logf(g_St[i]) - g_gtail[i];
            out[i] = v;
        }
    }
}

// ===========================================================================
// Merged launch: bx < GATHER_CTAS do the exact-gather; the rest run the
// fp8 GEMM + fused sum-exp (3-stage cp.async pipeline). Last CTA combines.
// ===========================================================================
__global__ void __launch_bounds__(256, 2) fp8_sumexp_multi(MPAR P)
{
    extern __shared__ __align__(16) uint32_t dyn[];
    __shared__ float rsum[128];

    const int bx = blockIdx.x;
    const int tid  = threadIdx.x;
    const int lane = tid & 31;
    const int wid  = tid >> 5;

    if (bx < GATHER_CTAS) {
        for (int t = bx * 8 + wid; t < 2 * NROWS; t += GATHER_CTAS * 8) {
            if (t < NROWS) {
                int row = t;
                int c = g_cluster[row];
                int col = (c == 0) ? P.target[row] : (HEAD_SIZE - c);
                const float4* pr = (const float4*)(g_proj + (size_t)row * PCW);
                const float4* wr = (const float4*)(P.w0 + (size_t)col * 1024);
                float s = 0.f;
                for (int i = lane; i < 256; i += 32) {
                    float4 a = pr[i], b = wr[i];
                    s += a.x * b.x + a.y * b.y + a.z * b.z + a.w * b.w;
                }
#pragma unroll
                for (int o = 16; o; o >>= 1) s += __shfl_down_sync(0xffffffffu, s, o);
                if (lane == 0) g_ghead[row] = s + P.b0[col];
            } else {
                int row = t - NROWS;
                int c = g_cluster[row];
                if (c == 0) continue;
                const float* pr; const float* W; const float* bb; int K, off;
                if (c == 1)      { pr = g_proj + (size_t)row * PCW + 1024; W = P.w1; bb = P.b1; K = 256; off = 20000; }
                else if (c == 2) { pr = g_proj + (size_t)row * PCW + 1280; W = P.w2; bb = P.b2; K = 64;  off = 40000; }
                else             { pr = g_proj + (size_t)row * PCW + 1344; W = P.w3; bb = P.b3; K = 16;  off = 200000; }
                int ti = P.target[row] - off;
                float s = 0.f;
                for (int k = lane; k < K; k += 32) s += pr[k] * W[(size_t)ti * K + k];
#pragma unroll
                for (int o = 16; o; o >>= 1) s += __shfl_down_sync(0xffffffffu, s, o);
                if (lane == 0) g_gtail[row] = s + bb[ti];
            }
        }
        cta_finish(P.out);
        return;
    }

    const int pi = (bx >= P.p[1].base) + (bx >= P.p[2].base) + (bx >= P.p[3].base);
    const SEP sp = P.p[pi];
    const int local = bx - sp.base;
    const int tileX = local % sp.nx;
    const int tileY = local / sp.nx;

    const int count = sp.countPtr ? *sp.countPtr : NROWS;
    const int rowBase = tileY * 128;
    if (rowBase >= count) { cta_finish(P.out); return; }
    const int colBase = tileX * 128;
    const int Nc = sp.Nc, K = sp.K;

    const int mBase = (wid & 1) * 64;
    const int nBase = (wid >> 1) * 32;
    const int lq = lane >> 2;
    const int lr = lane & 3;

    if (tid < 128) rsum[tid] = 0.f;

    const int ar   = tid >> 1;
    const int half = tid & 1;
    const int gA   = rowBase + ar;
    const bool aval = (gA < count);
    const int arow = aval ? (sp.rowmap ? sp.rowmap[gA] : gA) : 0;
    const uint8_t* Ag = sp.A + (size_t)arow * PCWP + half * 32;
    int gB = colBase + ar; if (gB >= Nc) gB = Nc - 1;
    const uint8_t* Bg = sp.B + (size_t)gB * K + half * 32;

    const uint32_t smb = (uint32_t)__cvta_generic_to_shared(dyn);
    const uint32_t aSlot = smb + (ar * LDW + half * 8) * 4;
    const uint32_t bSlot = smb + MATB + (ar * LDW + half * 8) * 4;
    const uint32_t aFrag = smb + ((mBase + (lane & 15)) * LDW + (lane >> 4) * 4) * 4;
    const uint32_t bFrag = smb + MATB + ((nBase + lane) * LDW) * 4;

    float acc[4][4][4];
#pragma unroll
    for (int i = 0; i < 4; i++)
#pragma unroll
        for (int j = 0; j < 4; j++)
#pragma unroll
            for (int r = 0; r < 4; r++) acc[i][j][r] = 0.f;

    const int nch = K >> 6;

    CP_ASYNC16(aSlot, Ag);          CP_ASYNC16(aSlot + 16, Ag + 16);
    CP_ASYNC16(bSlot, Bg);          CP_ASYNC16(bSlot + 16, Bg + 16);
    CP_COMMIT();
    if (nch > 1) {
        CP_ASYNC16(aSlot + STAGEB, Ag + 64);      CP_ASYNC16(aSlot + STAGEB + 16, Ag + 80);
        CP_ASYNC16(bSlot + STAGEB, Bg + 64);      CP_ASYNC16(bSlot + STAGEB + 16, Bg + 80);
        CP_COMMIT();
    }

    int buf = 0;
    for (int c = 0; c < nch; ++c) {
        if (c + 1 < nch) CP_WAIT(1); else CP_WAIT(0);
        __syncthreads();

        if (c + 2 < nch) {
            int nb = buf + 2; if (nb >= NSTAGE) nb -= NSTAGE;
            const uint32_t off = nb * STAGEB;
            const uint8_t* an = Ag + ((c + 2) << 6);
            const uint8_t* bn = Bg + ((c + 2) << 6);
            CP_ASYNC16(aSlot + off, an); CP_ASYNC16(aSlot + off + 16, an + 16);
            CP_ASYNC16(bSlot + off, bn); CP_ASYNC16(bSlot + off + 16, bn + 16);
            CP_COMMIT();
        }

        const uint32_t aB = aFrag + buf * STAGEB;
        const uint32_t bB = bFrag + buf * STAGEB;
#pragma unroll
        for (int cc = 0; cc < 2; ++cc) {
            uint32_t af[4][4], b0r[4], b1r[4];
            LDSM4(b0r[0], b0r[1], b0r[2], b0r[3], bB + cc * 32);
            LDSM4(b1r[0], b1r[1], b1r[2], b1r[3], bB + cc * 32 + 16);
#pragma unroll
            for (int mt = 0; mt < 4; mt++)
                LDSM4(af[mt][0], af[mt][1], af[mt][2], af[mt][3],
                      aB + mt * (16 * LDW * 4) + cc * 32);
#pragma unroll
            for (int mt = 0; mt < 4; mt++)
#pragma unroll
                for (int nt = 0; nt < 4; nt++)
                    MMA_FP8(acc[mt][nt],
                            af[mt][0], af[mt][1], af[mt][2], af[mt][3],
                            b0r[nt], b1r[nt]);
        }

        if (++buf == NSTAGE) buf = 0;
    }

    float rs[4][2];
#pragma unroll
    for (int mt = 0; mt < 4; mt++) { rs[mt][0] = 0.f; rs[mt][1] = 0.f; }

    const float* bptr = sp.bias + colBase + nBase;
    if (colBase + 128 <= Nc) {
#pragma unroll
        for (int nt = 0; nt < 4; nt++) {
            int cc0 = nt * 8 + 2 * lr;
            float bv0 = bptr[cc0] * LOG2E;
            float bv1 = bptr[cc0 + 1] * LOG2E;
#pragma unroll
            for (int mt = 0; mt < 4; mt++) {
                rs[mt][0] += exp2f(fmaf(acc[mt][nt][0], INV64_LOG2E, bv0));
                rs[mt][1] += exp2f(fmaf(acc[mt][nt][2], INV64_LOG2E, bv0));
                rs[mt][0] += exp2f(fmaf(acc[mt][nt][1], INV64_LOG2E, bv1));
                rs[mt][1] += exp2f(fmaf(acc[mt][nt][3], INV64_LOG2E, bv1));
            }
        }
    } else {
#pragma unroll
        for (int nt = 0; nt < 4; nt++) {
            int gc = colBase + nBase + nt * 8 + 2 * lr;
            bool v0 = gc < Nc, v1 = (gc + 1) < Nc;
            float bv0 = v0 ? sp.bias[gc] * LOG2E : 0.f;
            float bv1 = v1 ? sp.bias[gc + 1] * LOG2E : 0.f;
#pragma unroll
            for (int mt = 0; mt < 4; mt++) {
                if (v0) {
                    rs[mt][0] += exp2f(fmaf(acc[mt][nt][0], INV64_LOG2E, bv0));
                    rs[mt][1] += exp2f(fmaf(acc[mt][nt][2], INV64_LOG2E, bv0));
                }
                if (v1) {
                    rs[mt][0] += exp2f(fmaf(acc[mt][nt][1], INV64_LOG2E, bv1));
                    rs[mt][1] += exp2f(fmaf(acc[mt][nt][3], INV64_LOG2E, bv1));
                }
            }
        }
    }
#pragma unroll
    for (int mt = 0; mt < 4; mt++)
#pragma unroll
        for (int h = 0; h < 2; h++) {
            float v = rs[mt][h];
            v += __shfl_xor_sync(0xffffffffu, v, 1);
            v += __shfl_xor_sync(0xffffffffu, v, 2);
            if (lr == 0)
                atomicAdd(&rsum[mBase + mt * 16 + h * 8 + lq], v);
        }
    __syncthreads();
    if (tid < 128) {
        int gr = rowBase + tid;
        if (gr < count) {
            int n = sp.rowmap ? sp.rowmap[gr] : gr;
            atomicAdd(&sp.Ssum[n], rsum[tid]);
        }
    }

    cta_finish(P.out);
}

// ===========================================================================
// tf32 proj GEMM: proj = hidden @ [p0|p1|p2|p3] directly (no concat).
// ===========================================================================
__global__ void __launch_bounds__(256, 2) proj_gemm(
    const float* __restrict__ A,
    const float* __restrict__ p0, const float* __restrict__ p1,
    const float* __restrict__ p2, const float* __restrict__ p3,
    float* __restrict__ C, uint8_t* __restrict__ C8)
{
    const int Nc = PCW, K = 1024;
    __shared__ uint32_t As[128 * LDW];
    __shared__ uint32_t Bs[128 * LDW];

    const int rowBase = blockIdx.y * 128;
    const int colBase = blockIdx.x * 128;

    const int tid  = threadIdx.x;
    const int lane = tid & 31;
    const int wid  = tid >> 5;
    const int mBase = (wid & 1) * 64;
    const int nBase = (wid >> 1) * 32;
    const int lq = lane >> 2;
    const int lr = lane & 3;

    const int ar  = tid >> 1;
    const int akk = (tid & 1) * 8;
    const float* Aptr = A + (size_t)(rowBase + ar) * K + akk;

    const int bkk = tid >> 4;
    const int br  = (tid & 15) * 8;
    const int gc  = colBase + br;
    const bool bval = gc < Nc;
    const float* src; int snc, scol;
    if (gc < 1024)      { src = p0; snc = 1024; scol = gc; }
    else if (gc < 1280) { src = p1; snc = 256;  scol = gc - 1024; }
    else if (gc < 1344) { src = p2; snc = 64;   scol = gc - 1280; }
    else                { src = p3; snc = 16;   scol = bval ? gc - 1344 : 0; }
    const float* Bptr = src + scol;

    const float4 fz = make_float4(0.f, 0.f, 0.f, 0.f);
    float4 aR0, aR1, bR0, bR1;
    aR0 = *(const float4*)(Aptr);
    aR1 = *(const float4*)(Aptr + 4);
    bR0 = bval ? *(const float4*)(Bptr + (size_t)bkk * snc)     : fz;
    bR1 = bval ? *(const float4*)(Bptr + (size_t)bkk * snc + 4) : fz;

    float acc[4][4][4];
#pragma unroll
    for (int i = 0; i < 4; i++)
#pragma unroll
        for (int j = 0; j < 4; j++)
#pragma unroll
            for (int r = 0; r < 4; r++) acc[i][j][r] = 0.f;

    for (int k0 = 0; k0 < K; k0 += 16) {
        {
            uint32_t* ap = &As[ar * LDW + akk];
            ap[0] = f2tf(aR0.x); ap[1] = f2tf(aR0.y); ap[2] = f2tf(aR0.z); ap[3] = f2tf(aR0.w);
            ap[4] = f2tf(aR1.x); ap[5] = f2tf(aR1.y); ap[6] = f2tf(aR1.z); ap[7] = f2tf(aR1.w);
            float v[8] = {bR0.x, bR0.y, bR0.z, bR0.w, bR1.x, bR1.y, bR1.z, bR1.w};
#pragma unroll
            for (int q = 0; q < 8; q++) Bs[(br + q) * LDW + bkk] = f2tf(v[q]);
        }
        __syncthreads();

        const int kn = k0 + 16;
        if (kn < K) {
            aR0 = *(const float4*)(Aptr + kn);
            aR1 = *(const float4*)(Aptr + kn + 4);
            bR0 = bval ? *(const float4*)(Bptr + (size_t)(kn + bkk) * snc)     : fz;
            bR1 = bval ? *(const float4*)(Bptr + (size_t)(kn + bkk) * snc + 4) : fz;
        }

#pragma unroll
        for (int ks = 0; ks < 16; ks += 8) {
            uint32_t af[4][4], bf[4][2];
#pragma unroll
            for (int mt = 0; mt < 4; mt++) {
                int r = mBase + mt * 16 + lq;
                int c = ks + lr;
                af[mt][0] = As[r * LDW + c];
                af[mt][1] = As[(r + 8) * LDW + c];
                af[mt][2] = As[r * LDW + c + 4];
                af[mt][3] = As[(r + 8) * LDW + c + 4];
            }
#pragma unroll
            for (int nt = 0; nt < 4; nt++) {
                int n = nBase + nt * 8 + lq;
                bf[nt][0] = Bs[n * LDW + ks + lr];
                bf[nt][1] = Bs[n * LDW + ks + 4 + lr];
            }
#pragma unroll
            for (int mt = 0; mt < 4; mt++)
#pragma unroll
                for (int nt = 0; nt < 4; nt++)
                    MMA_TF32(acc[mt][nt], af[mt], bf[nt]);
        }
        __syncthreads();
    }

#pragma unroll
    for (int mt = 0; mt < 4; mt++) {
        int r0 = rowBase + mBase + mt * 16 + lq;
#pragma unroll
        for (int nt = 0; nt < 4; nt++) {
            int c2 = colBase + nBase + nt * 8 + 2 * lr;
            if (c2 < Nc) {
                float* q0 = C + (size_t)r0 * Nc + c2;
                float* q1 = C + (size_t)(r0 + 8) * Nc + c2;
                q0[0] = acc[mt][nt][0]; q0[1] = acc[mt][nt][1];
                q1[0] = acc[mt][nt][2]; q1[1] = acc[mt][nt][3];
                ((uint16_t*)C8)[((size_t)r0 * PCWP + c2) >> 1] =
                    pack_e4m3(acc[mt][nt][0] * 8.f, acc[mt][nt][1] * 8.f);
                ((uint16_t*)C8)[((size_t)(r0 + 8) * PCWP + c2) >> 1] =
                    pack_e4m3(acc[mt][nt][2] * 8.f, acc[mt][nt][3] * 8.f);
            }
        }
    }
}

// ---------------- wconv (+prep in CTA 0) ------------------------------------
__global__ void wconv_kernel(
    const float4* __restrict__ w0, const float4* __restrict__ w1,
    const float4* __restrict__ w2, const float4* __restrict__ w3,
    const int* __restrict__ target)
{
    if (blockIdx.x == 0) {
        // prep: init sums, classify rows, build rowlists
        int tid = threadIdx.x;
        if (tid == 0) g_done = 0;
        if (tid < 3) g_count[tid] = 0;
        for (int i = tid; i < NROWS; i += blockDim.x) {
            g_S0[i] = 0.f; g_St[i] = 0.f;
        }
        __syncthreads();
        for (int i = tid; i < NROWS; i += blockDim.x) {
            int t = target[i];
            int c = (t < 20000) ? 0 : (t < 40000) ? 1 : (t < 200000) ? 2 : 3;
            g_cluster[i] = c;
            if (c > 0) {
                int idx = atomicAdd(&g_count[c - 1], 1);
                g_rowlist[(c - 1) * NROWS + idx] = i;
            }
        }
    }

    const int T1 = 5120768;           // w0: 20003*1024/4
    const int T2 = T1 + 1280000;      // w1: 20000*256/4
    const int T3 = T2 + 2560000;      // w2: 160000*64/4
    const int T4 = T3 + 270940;       // w3 data: 67735*16/4
    const int T5 = T4 + 812820;       // w3 pad zeros: 67735*12
    const int T6 = T5 + 12288;        // proj8 pad zeros: 1024*12
    for (int i = blockIdx.x * blockDim.x + threadIdx.x; i < T6;
         i += gridDim.x * blockDim.x) {
        if (i < T1) {
            ((uint32_t*)g_w0b)[i] = pack4_e4m3_x8(w0[i]);
        } else if (i < T2) {
            int j = i - T1;
            ((uint32_t*)g_w1b)[j] = pack4_e4m3_x8(w1[j]);
        } else if (i < T3) {
            int j = i - T2;
            ((uint32_t*)g_w2b)[j] = pack4_e4m3_x8(w2[j]);
        } else if (i < T4) {
            int j = i - T3;
            int row = j >> 2, q = j & 3;
            ((uint32_t*)g_w3b)[row * 16 + q] = pack4_e4m3_x8(w3[j]);
        } else if (i < T5) {
            int j = i - T4;
            int row = j / 12, word = j - row * 12;
            ((uint32_t*)g_w3b)[row * 16 + 4 + word] = 0u;
        } else {
            int j = i - T5;
            int row = j / 12, word = j - row * 12;
            ((uint32_t*)g_proj8)[row * 352 + 340 + word] = 0u;
        }
    }
}

// ---------------- launch ----------------------------------------------------
extern "C" void kernel_launch(void* const* d_in, const int* in_sizes, int n_in,
                              void* d_out, int out_size) {
    const float* hidden = (const float*)d_in[0];
    const int*   target = (const int*)d_in[1];
    const float* w0 = (const float*)d_in[2];
    const float* b0 = (const float*)d_in[3];
    const float* p0 = (const float*)d_in[4];
    const float* w1 = (const float*)d_in[5];
    const float* b1 = (const float*)d_in[6];
    const float* p1 = (const float*)d_in[7];
    const float* w2 = (const float*)d_in[8];
    const float* b2 = (const float*)d_in[9];
    const float* p2 = (const float*)d_in[10];
    const float* w3 = (const float*)d_in[11];
    const float* b3 = (const float*)d_in[12];
    const float* p3 = (const float*)d_in[13];
    float* out = (float*)d_out;

    float *proj, *S0, *St;
    uint8_t *proj8, *w0b, *w1b, *w2b, *w3b;
    int *rowlist, *cnt;
    cudaGetSymbolAddress((void**)&proj, g_proj);
    cudaGetSymbolAddress((void**)&proj8, g_proj8);
    cudaGetSymbolAddress((void**)&w0b, g_w0b);
    cudaGetSymbolAddress((void**)&w1b, g_w1b);
    cudaGetSymbolAddress((void**)&w2b, g_w2b);
    cudaGetSymbolAddress((void**)&w3b, g_w3b);
    cudaGetSymbolAddress((void**)&S0, g_S0);
    cudaGetSymbolAddress((void**)&St, g_St);
    cudaGetSymbolAddress((void**)&rowlist, g_rowlist);
    cudaGetSymbolAddress((void**)&cnt, g_count);

    static bool attrDone = false;
    if (!attrDone) {
        cudaFuncSetAttribute(fp8_sumexp_multi,
                             cudaFuncAttributeMaxDynamicSharedMemorySize, DSMEM);
        attrDone = true;
    }

    // 1) wconv + prep (single stream)
    wconv_kernel<<<2048, 256>>>((const float4*)w0, (const float4*)w1,
                                (const float4*)w2, (const float4*)w3, target);

    // 2) proj = hidden @ [p0|p1|p2|p3] (tf32, fp32 + fp8 outputs)
    proj_gemm<<<dim3(11, 8, 1), 256>>>(hidden, p0, p1, p2, p3, proj, proj8);

    // 3) merged launch: gather + 4 fp8 sum-exp GEMMs + last-CTA combine
    MPAR P;
    P.p[0] = { proj8,        w0b, b0, S0, HEAD_SIZE, 1024, 157,
               GATHER_CTAS, nullptr, nullptr };                      // 1256
    P.p[1] = { proj8 + 1024, w1b, b1, St, 20000, 256, 157,
               GATHER_CTAS + 1256, rowlist + 0 * NROWS, cnt + 0 };   // 1256
    P.p[2] = { proj8 + 1344, w3b, b3, St, 67735, 64, 530,
               GATHER_CTAS + 2512, rowlist + 2 * NROWS, cnt + 2 };   // 4240
    P.p[3] = { proj8 + 1280, w2b, b2, St, 160000, 64, 1250,
               GATHER_CTAS + 6752, rowlist + 1 * NROWS, cnt + 1 };   // 10000
    P.w0 = w0; P.b0 = b0; P.w1 = w1; P.b1 = b1;
    P.w2 = w2; P.b2 = b2; P.w3 = w3; P.b3 = b3;
    P.target = target;
    P.out = out;
    fp8_sumexp_multi<<<GATHER_CTAS + 16752, 256, DSMEM>>>(P);
}

// round 16
// speedup vs baseline: 1.1836x; 1.1068x over previous
#include <cuda_runtime.h>
#include <cuda_bf16.h>
#include <math.h>
#include <stdint.h>

// ---------------------------------------------------------------------------
// AdaptiveLogSoftmax NLL — single stream, 4 launches (R13 + prep folded
// into wconv CTA0; no fences/events — those regressed in R12/R14/R15).
//   wconv+prep: CTA0 classifies rows; all CTAs convert weights -> e4m3 (x8)
//   proj:       proj = hidden @ [p0|p1|p2|p3] (tf32, direct B, no concat)
//   merged:     64 gather CTAs + head/tail1/tail3/tail2 fp8 sum-exp GEMMs
//   combine:    final NLL
// ---------------------------------------------------------------------------

#define NROWS 1024
#define HEAD_SIZE 20003
#define PCW 1360
#define PCWP 1408
#define LOG2E 1.4426950408889634f
#define INV64_LOG2E (LOG2E / 64.f)
#define GATHER_CTAS 64

__device__ __align__(16) float    g_proj[NROWS * PCW];
__device__ __align__(16) uint8_t  g_proj8[NROWS * PCWP];
__device__ __align__(16) uint8_t  g_w0b[20003 * 1024];
__device__ __align__(16) uint8_t  g_w1b[20000 * 256];
__device__ __align__(16) uint8_t  g_w2b[160000 * 64];
__device__ __align__(16) uint8_t  g_w3b[67735 * 64];
__device__ float g_S0[NROWS];
__device__ float g_St[NROWS];
__device__ float g_ghead[NROWS];
__device__ float g_gtail[NROWS];
__device__ int   g_rowlist[3 * NROWS];
__device__ int   g_count[3];
__device__ int   g_cluster[NROWS];

// ---------------- helpers ---------------------------------------------------
__device__ __forceinline__ uint32_t f2tf(float f) {
    uint32_t r;
    asm("cvt.rna.tf32.f32 %0, %1;" : "=r"(r) : "f"(f));
    return r;
}
__device__ __forceinline__ uint16_t pack_e4m3(float lo, float hi) {
    uint16_t r;
    asm("cvt.rn.satfinite.e4m3x2.f32 %0, %1, %2;" : "=h"(r) : "f"(hi), "f"(lo));
    return r;
}
__device__ __forceinline__ uint32_t pack4_e4m3_x8(float4 v) {
    uint16_t l = pack_e4m3(v.x * 8.f, v.y * 8.f);
    uint16_t h = pack_e4m3(v.z * 8.f, v.w * 8.f);
    return (uint32_t)l | ((uint32_t)h << 16);
}

#define MMA_TF32(c, a, b)                                                     \
    asm volatile(                                                             \
        "mma.sync.aligned.m16n8k8.row.col.f32.tf32.tf32.f32 "                 \
        "{%0,%1,%2,%3},{%4,%5,%6,%7},{%8,%9},{%0,%1,%2,%3};"                  \
        : "+f"(c[0]), "+f"(c[1]), "+f"(c[2]), "+f"(c[3])                      \
        : "r"(a[0]), "r"(a[1]), "r"(a[2]), "r"(a[3]), "r"(b[0]), "r"(b[1]))

#define MMA_FP8(c, a0, a1, a2, a3, b0, b1)                                    \
    asm volatile(                                                             \
        "mma.sync.aligned.m16n8k32.row.col.f32.e4m3.e4m3.f32 "                \
        "{%0,%1,%2,%3},{%4,%5,%6,%7},{%8,%9},{%0,%1,%2,%3};"                  \
        : "+f"(c[0]), "+f"(c[1]), "+f"(c[2]), "+f"(c[3])                      \
        : "r"(a0), "r"(a1), "r"(a2), "r"(a3), "r"(b0), "r"(b1))

#define LDSM4(r0, r1, r2, r3, addr)                                           \
    asm volatile("ldmatrix.sync.aligned.m8n8.x4.shared.b16 {%0,%1,%2,%3}, [%4];" \
        : "=r"(r0), "=r"(r1), "=r"(r2), "=r"(r3) : "r"(addr))

#define CP_ASYNC16(smem, gptr)                                                \
    asm volatile("cp.async.cg.shared.global [%0], [%1], 16;"                  \
        :: "r"(smem), "l"(gptr) : "memory")
#define CP_COMMIT()  asm volatile("cp.async.commit_group;" ::: "memory")
#define CP_WAIT(n)   asm volatile("cp.async.wait_group %0;" :: "n"(n) : "memory")

#define LDW 20
#define MATB (128 * LDW * 4)
#define STAGEB (2 * MATB)
#define NSTAGE 3
#define DSMEM (NSTAGE * STAGEB)

// ---------------- merged problem table --------------------------------------
struct SEP {
    const uint8_t* A;
    const uint8_t* B;
    const float*   bias;
    float*         Ssum;
    int Nc, K, nx, base;
    const int* rowmap;
    const int* countPtr;
};
struct MPAR {
    SEP p[4];
    const float *w0, *b0, *w1, *b1, *w2, *b2, *w3, *b3;
    const int* target;
};

// ===========================================================================
// Merged launch: bx < GATHER_CTAS do the exact-gather; the rest run the
// fp8 GEMM + fused sum-exp (3-stage cp.async pipeline).
// ===========================================================================
__global__ void __launch_bounds__(256, 2) fp8_sumexp_multi(MPAR P)
{
    extern __shared__ __align__(16) uint32_t dyn[];
    __shared__ float rsum[128];

    const int bx = blockIdx.x;
    const int tid  = threadIdx.x;
    const int lane = tid & 31;
    const int wid  = tid >> 5;

    if (bx < GATHER_CTAS) {
        for (int t = bx * 8 + wid; t < 2 * NROWS; t += GATHER_CTAS * 8) {
            if (t < NROWS) {
                int row = t;
                int c = g_cluster[row];
                int col = (c == 0) ? P.target[row] : (HEAD_SIZE - c);
                const float4* pr = (const float4*)(g_proj + (size_t)row * PCW);
                const float4* wr = (const float4*)(P.w0 + (size_t)col * 1024);
                float s = 0.f;
                for (int i = lane; i < 256; i += 32) {
                    float4 a = pr[i], b = wr[i];
                    s += a.x * b.x + a.y * b.y + a.z * b.z + a.w * b.w;
                }
#pragma unroll
                for (int o = 16; o; o >>= 1) s += __shfl_down_sync(0xffffffffu, s, o);
                if (lane == 0) g_ghead[row] = s + P.b0[col];
            } else {
                int row = t - NROWS;
                int c = g_cluster[row];
                if (c == 0) continue;
                const float* pr; const float* W; const float* bb; int K, off;
                if (c == 1)      { pr = g_proj + (size_t)row * PCW + 1024; W = P.w1; bb = P.b1; K = 256; off = 20000; }
                else if (c == 2) { pr = g_proj + (size_t)row * PCW + 1280; W = P.w2; bb = P.b2; K = 64;  off = 40000; }
                else             { pr = g_proj + (size_t)row * PCW + 1344; W = P.w3; bb = P.b3; K = 16;  off = 200000; }
                int ti = P.target[row] - off;
                float s = 0.f;
                for (int k = lane; k < K; k += 32) s += pr[k] * W[(size_t)ti * K + k];
#pragma unroll
                for (int o = 16; o; o >>= 1) s += __shfl_down_sync(0xffffffffu, s, o);
                if (lane == 0) g_gtail[row] = s + bb[ti];
            }
        }
        return;
    }

    const int pi = (bx >= P.p[1].base) + (bx >= P.p[2].base) + (bx >= P.p[3].base);
    const SEP sp = P.p[pi];
    const int local = bx - sp.base;
    const int tileX = local % sp.nx;
    const int tileY = local / sp.nx;

    const int count = sp.countPtr ? *sp.countPtr : NROWS;
    const int rowBase = tileY * 128;
    if (rowBase >= count) return;
    const int colBase = tileX * 128;
    const int Nc = sp.Nc, K = sp.K;

    const int mBase = (wid & 1) * 64;
    const int nBase = (wid >> 1) * 32;
    const int lq = lane >> 2;
    const int lr = lane & 3;

    if (tid < 128) rsum[tid] = 0.f;

    const int ar   = tid >> 1;
    const int half = tid & 1;
    const int gA   = rowBase + ar;
    const bool aval = (gA < count);
    const int arow = aval ? (sp.rowmap ? sp.rowmap[gA] : gA) : 0;
    const uint8_t* Ag = sp.A + (size_t)arow * PCWP + half * 32;
    int gB = colBase + ar; if (gB >= Nc) gB = Nc - 1;
    const uint8_t* Bg = sp.B + (size_t)gB * K + half * 32;

    const uint32_t smb = (uint32_t)__cvta_generic_to_shared(dyn);
    const uint32_t aSlot = smb + (ar * LDW + half * 8) * 4;
    const uint32_t bSlot = smb + MATB + (ar * LDW + half * 8) * 4;
    const uint32_t aFrag = smb + ((mBase + (lane & 15)) * LDW + (lane >> 4) * 4) * 4;
    const uint32_t bFrag = smb + MATB + ((nBase + lane) * LDW) * 4;

    float acc[4][4][4];
#pragma unroll
    for (int i = 0; i < 4; i++)
#pragma unroll
        for (int j = 0; j < 4; j++)
#pragma unroll
            for (int r = 0; r < 4; r++) acc[i][j][r] = 0.f;

    const int nch = K >> 6;

    CP_ASYNC16(aSlot, Ag);          CP_ASYNC16(aSlot + 16, Ag + 16);
    CP_ASYNC16(bSlot, Bg);          CP_ASYNC16(bSlot + 16, Bg + 16);
    CP_COMMIT();
    if (nch > 1) {
        CP_ASYNC16(aSlot + STAGEB, Ag + 64);      CP_ASYNC16(aSlot + STAGEB + 16, Ag + 80);
        CP_ASYNC16(bSlot + STAGEB, Bg + 64);      CP_ASYNC16(bSlot + STAGEB + 16, Bg + 80);
        CP_COMMIT();
    }

    int buf = 0;
    for (int c = 0; c < nch; ++c) {
        if (c + 1 < nch) CP_WAIT(1); else CP_WAIT(0);
        __syncthreads();

        if (c + 2 < nch) {
            int nb = buf + 2; if (nb >= NSTAGE) nb -= NSTAGE;
            const uint32_t off = nb * STAGEB;
            const uint8_t* an = Ag + ((c + 2) << 6);
            const uint8_t* bn = Bg + ((c + 2) << 6);
            CP_ASYNC16(aSlot + off, an); CP_ASYNC16(aSlot + off + 16, an + 16);
            CP_ASYNC16(bSlot + off, bn); CP_ASYNC16(bSlot + off + 16, bn + 16);
            CP_COMMIT();
        }

        const uint32_t aB = aFrag + buf * STAGEB;
        const uint32_t bB = bFrag + buf * STAGEB;
#pragma unroll
        for (int cc = 0; cc < 2; ++cc) {
            uint32_t af[4][4], b0r[4], b1r[4];
            LDSM4(b0r[0], b0r[1], b0r[2], b0r[3], bB + cc * 32);
            LDSM4(b1r[0], b1r[1], b1r[2], b1r[3], bB + cc * 32 + 16);
#pragma unroll
            for (int mt = 0; mt < 4; mt++)
                LDSM4(af[mt][0], af[mt][1], af[mt][2], af[mt][3],
                      aB + mt * (16 * LDW * 4) + cc * 32);
#pragma unroll
            for (int mt = 0; mt < 4; mt++)
#pragma unroll
                for (int nt = 0; nt < 4; nt++)
                    MMA_FP8(acc[mt][nt],
                            af[mt][0], af[mt][1], af[mt][2], af[mt][3],
                            b0r[nt], b1r[nt]);
        }

        if (++buf == NSTAGE) buf = 0;
    }

    float rs[4][2];
#pragma unroll
    for (int mt = 0; mt < 4; mt++) { rs[mt][0] = 0.f; rs[mt][1] = 0.f; }

    const float* bptr = sp.bias + colBase + nBase;
    if (colBase + 128 <= Nc) {
#pragma unroll
        for (int nt = 0; nt < 4; nt++) {
            int cc0 = nt * 8 + 2 * lr;
            float bv0 = bptr[cc0] * LOG2E;
            float bv1 = bptr[cc0 + 1] * LOG2E;
#pragma unroll
            for (int mt = 0; mt < 4; mt++) {
                rs[mt][0] += exp2f(fmaf(acc[mt][nt][0], INV64_LOG2E, bv0));
                rs[mt][1] += exp2f(fmaf(acc[mt][nt][2], INV64_LOG2E, bv0));
                rs[mt][0] += exp2f(fmaf(acc[mt][nt][1], INV64_LOG2E, bv1));
                rs[mt][1] += exp2f(fmaf(acc[mt][nt][3], INV64_LOG2E, bv1));
            }
        }
    } else {
#pragma unroll
        for (int nt = 0; nt < 4; nt++) {
            int gc = colBase + nBase + nt * 8 + 2 * lr;
            bool v0 = gc < Nc, v1 = (gc + 1) < Nc;
            float bv0 = v0 ? sp.bias[gc] * LOG2E : 0.f;
            float bv1 = v1 ? sp.bias[gc + 1] * LOG2E : 0.f;
#pragma unroll
            for (int mt = 0; mt < 4; mt++) {
                if (v0) {
                    rs[mt][0] += exp2f(fmaf(acc[mt][nt][0], INV64_LOG2E, bv0));
                    rs[mt][1] += exp2f(fmaf(acc[mt][nt][2], INV64_LOG2E, bv0));
                }
                if (v1) {
                    rs[mt][0] += exp2f(fmaf(acc[mt][nt][1], INV64_LOG2E, bv1));
                    rs[mt][1] += exp2f(fmaf(acc[mt][nt][3], INV64_LOG2E, bv1));
                }
            }
        }
    }
#pragma unroll
    for (int mt = 0; mt < 4; mt++)
#pragma unroll
        for (int h = 0; h < 2; h++) {
            float v = rs[mt][h];
            v += __shfl_xor_sync(0xffffffffu, v, 1);
            v += __shfl_xor_sync(0xffffffffu, v, 2);
            if (lr == 0)
                atomicAdd(&rsum[mBase + mt * 16 + h * 8 + lq], v);
        }
    __syncthreads();
    if (tid < 128) {
        int gr = rowBase + tid;
        if (gr < count) {
            int n = sp.rowmap ? sp.rowmap[gr] : gr;
            atomicAdd(&sp.Ssum[n], rsum[tid]);
        }
    }
}

// ===========================================================================
// tf32 proj GEMM: proj = hidden @ [p0|p1|p2|p3] directly (no concat).
// ===========================================================================
__global__ void __launch_bounds__(256, 2) proj_gemm(
    const float* __restrict__ A,
    const float* __restrict__ p0, const float* __restrict__ p1,
    const float* __restrict__ p2, const float* __restrict__ p3,
    float* __restrict__ C, uint8_t* __restrict__ C8)
{
    const int Nc = PCW, K = 1024;
    __shared__ uint32_t As[128 * LDW];
    __shared__ uint32_t Bs[128 * LDW];

    const int rowBase = blockIdx.y * 128;
    const int colBase = blockIdx.x * 128;

    const int tid  = threadIdx.x;
    const int lane = tid & 31;
    const int wid  = tid >> 5;
    const int mBase = (wid & 1) * 64;
    const int nBase = (wid >> 1) * 32;
    const int lq = lane >> 2;
    const int lr = lane & 3;

    const int ar  = tid >> 1;
    const int akk = (tid & 1) * 8;
    const float* Aptr = A + (size_t)(rowBase + ar) * K + akk;

    const int bkk = tid >> 4;
    const int br  = (tid & 15) * 8;
    const int gc  = colBase + br;
    const bool bval = gc < Nc;
    const float* src; int snc, scol;
    if (gc < 1024)      { src = p0; snc = 1024; scol = gc; }
    else if (gc < 1280) { src = p1; snc = 256;  scol = gc - 1024; }
    else if (gc < 1344) { src = p2; snc = 64;   scol = gc - 1280; }
    else                { src = p3; snc = 16;   scol = bval ? gc - 1344 : 0; }
    const float* Bptr = src + scol;

    const float4 fz = make_float4(0.f, 0.f, 0.f, 0.f);
    float4 aR0, aR1, bR0, bR1;
    aR0 = *(const float4*)(Aptr);
    aR1 = *(const float4*)(Aptr + 4);
    bR0 = bval ? *(const float4*)(Bptr + (size_t)bkk * snc)     : fz;
    bR1 = bval ? *(const float4*)(Bptr + (size_t)bkk * snc + 4) : fz;

    float acc[4][4][4];
#pragma unroll
    for (int i = 0; i < 4; i++)
#pragma unroll
        for (int j = 0; j < 4; j++)
#pragma unroll
            for (int r = 0; r < 4; r++) acc[i][j][r] = 0.f;

    for (int k0 = 0; k0 < K; k0 += 16) {
        {
            uint32_t* ap = &As[ar * LDW + akk];
            ap[0] = f2tf(aR0.x); ap[1] = f2tf(aR0.y); ap[2] = f2tf(aR0.z); ap[3] = f2tf(aR0.w);
            ap[4] = f2tf(aR1.x); ap[5] = f2tf(aR1.y); ap[6] = f2tf(aR1.z); ap[7] = f2tf(aR1.w);
            float v[8] = {bR0.x, bR0.y, bR0.z, bR0.w, bR1.x, bR1.y, bR1.z, bR1.w};
#pragma unroll
            for (int q = 0; q < 8; q++) Bs[(br + q) * LDW + bkk] = f2tf(v[q]);
        }
        __syncthreads();

        const int kn = k0 + 16;
        if (kn < K) {
            aR0 = *(const float4*)(Aptr + kn);
            aR1 = *(const float4*)(Aptr + kn + 4);
            bR0 = bval ? *(const float4*)(Bptr + (size_t)(kn + bkk) * snc)     : fz;
            bR1 = bval ? *(const float4*)(Bptr + (size_t)(kn + bkk) * snc + 4) : fz;
        }

#pragma unroll
        for (int ks = 0; ks < 16; ks += 8) {
            uint32_t af[4][4], bf[4][2];
#pragma unroll
            for (int mt = 0; mt < 4; mt++) {
                int r = mBase + mt * 16 + lq;
                int c = ks + lr;
                af[mt][0] = As[r * LDW + c];
                af[mt][1] = As[(r + 8) * LDW + c];
                af[mt][2] = As[r * LDW + c + 4];
                af[mt][3] = As[(r + 8) * LDW + c + 4];
            }
#pragma unroll
            for (int nt = 0; nt < 4; nt++) {
                int n = nBase + nt * 8 + lq;
                bf[nt][0] = Bs[n * LDW + ks + lr];
                bf[nt][1] = Bs[n * LDW + ks + 4 + lr];
            }
#pragma unroll
            for (int mt = 0; mt < 4; mt++)
#pragma unroll
                for (int nt = 0; nt < 4; nt++)
                    MMA_TF32(acc[mt][nt], af[mt], bf[nt]);
        }
        __syncthreads();
    }

#pragma unroll
    for (int mt = 0; mt < 4; mt++) {
        int r0 = rowBase + mBase + mt * 16 + lq;
#pragma unroll
        for (int nt = 0; nt < 4; nt++) {
            int c2 = colBase + nBase + nt * 8 + 2 * lr;
            if (c2 < Nc) {
                float* q0 = C + (size_t)r0 * Nc + c2;
                float* q1 = C + (size_t)(r0 + 8) * Nc + c2;
                q0[0] = acc[mt][nt][0]; q0[1] = acc[mt][nt][1];
                q1[0] = acc[mt][nt][2]; q1[1] = acc[mt][nt][3];
                ((uint16_t*)C8)[((size_t)r0 * PCWP + c2) >> 1] =
                    pack_e4m3(acc[mt][nt][0] * 8.f, acc[mt][nt][1] * 8.f);
                ((uint16_t*)C8)[((size_t)(r0 + 8) * PCWP + c2) >> 1] =
                    pack_e4m3(acc[mt][nt][2] * 8.f, acc[mt][nt][3] * 8.f);
            }
        }
    }
}

// ---------------- wconv (+prep in CTA 0) ------------------------------------
__global__ void wconv_kernel(
    const float4* __restrict__ w0, const float4* __restrict__ w1,
    const float4* __restrict__ w2, const float4* __restrict__ w3,
    const int* __restrict__ target)
{
    if (blockIdx.x == 0) {
        int tid = threadIdx.x;
        if (tid < 3) g_count[tid] = 0;
        for (int i = tid; i < NROWS; i += blockDim.x) {
            g_S0[i] = 0.f; g_St[i] = 0.f;
        }
        __syncthreads();
        for (int i = tid; i < NROWS; i += blockDim.x) {
            int t = target[i];
            int c = (t < 20000) ? 0 : (t < 40000) ? 1 : (t < 200000) ? 2 : 3;
            g_cluster[i] = c;
            if (c > 0) {
                int idx = atomicAdd(&g_count[c - 1], 1);
                g_rowlist[(c - 1) * NROWS + idx] = i;
            }
        }
    }

    const int T1 = 5120768;           // w0: 20003*1024/4
    const int T2 = T1 + 1280000;      // w1: 20000*256/4
    const int T3 = T2 + 2560000;      // w2: 160000*64/4
    const int T4 = T3 + 270940;       // w3 data: 67735*16/4
    const int T5 = T4 + 812820;       // w3 pad zeros: 67735*12
    const int T6 = T5 + 12288;        // proj8 pad zeros: 1024*12
    for (int i = blockIdx.x * blockDim.x + threadIdx.x; i < T6;
         i += gridDim.x * blockDim.x) {
        if (i < T1) {
            ((uint32_t*)g_w0b)[i] = pack4_e4m3_x8(w0[i]);
        } else if (i < T2) {
            int j = i - T1;
            ((uint32_t*)g_w1b)[j] = pack4_e4m3_x8(w1[j]);
        } else if (i < T3) {
            int j = i - T2;
            ((uint32_t*)g_w2b)[j] = pack4_e4m3_x8(w2[j]);
        } else if (i < T4) {
            int j = i - T3;
            int row = j >> 2, q = j & 3;
            ((uint32_t*)g_w3b)[row * 16 + q] = pack4_e4m3_x8(w3[j]);
        } else if (i < T5) {
            int j = i - T4;
            int row = j / 12, word = j - row * 12;
            ((uint32_t*)g_w3b)[row * 16 + 4 + word] = 0u;
        } else {
            int j = i - T5;
            int row = j / 12, word = j - row * 12;
            ((uint32_t*)g_proj8)[row * 352 + 340 + word] = 0u;
        }
    }
}

__global__ void combine_kernel(float* __restrict__ out, int n) {
    int i = blockIdx.x * blockDim.x + threadIdx.x;
    if (i >= n) return;
    float v = logf(g_S0[i]) - g_ghead[i];
    if (g_cluster[i] > 0) v += logf(g_St[i]) - g_gtail[i];
    out[i] = v;
}

// ---------------- launch ----------------------------------------------------
extern "C" void kernel_launch(void* const* d_in, const int* in_sizes, int n_in,
                              void* d_out, int out_size) {
    const float* hidden = (const float*)d_in[0];
    const int*   target = (const int*)d_in[1];
    const float* w0 = (const float*)d_in[2];
    const float* b0 = (const float*)d_in[3];
    const float* p0 = (const float*)d_in[4];
    const float* w1 = (const float*)d_in[5];
    const float* b1 = (const float*)d_in[6];
    const float* p1 = (const float*)d_in[7];
    const float* w2 = (const float*)d_in[8];
    const float* b2 = (const float*)d_in[9];
    const float* p2 = (const float*)d_in[10];
    const float* w3 = (const float*)d_in[11];
    const float* b3 = (const float*)d_in[12];
    const float* p3 = (const float*)d_in[13];
    float* out = (float*)d_out;

    float *proj, *S0, *St;
    uint8_t *proj8, *w0b, *w1b, *w2b, *w3b;
    int *rowlist, *cnt;
    cudaGetSymbolAddress((void**)&proj, g_proj);
    cudaGetSymbolAddress((void**)&proj8, g_proj8);
    cudaGetSymbolAddress((void**)&w0b, g_w0b);
    cudaGetSymbolAddress((void**)&w1b, g_w1b);
    cudaGetSymbolAddress((void**)&w2b, g_w2b);
    cudaGetSymbolAddress((void**)&w3b, g_w3b);
    cudaGetSymbolAddress((void**)&S0, g_S0);
    cudaGetSymbolAddress((void**)&St, g_St);
    cudaGetSymbolAddress((void**)&rowlist, g_rowlist);
    cudaGetSymbolAddress((void**)&cnt, g_count);

    const int N = NROWS;

    static bool attrDone = false;
    if (!attrDone) {
        cudaFuncSetAttribute(fp8_sumexp_multi,
                             cudaFuncAttributeMaxDynamicSharedMemorySize, DSMEM);
        attrDone = true;
    }

    // 1) wconv + prep
    wconv_kernel<<<2048, 256>>>((const float4*)w0, (const float4*)w1,
                                (const float4*)w2, (const float4*)w3, target);

    // 2) proj = hidden @ [p0|p1|p2|p3]  (tf32, fp32 + fp8 outputs)
    proj_gemm<<<dim3(11, 8, 1), 256>>>(hidden, p0, p1, p2, p3, proj, proj8);

    // 3) merged launch: gather + 4 fp8 sum-exp GEMMs
    MPAR P;
    P.p[0] = { proj8,        w0b, b0, S0, HEAD_SIZE, 1024, 157,
               GATHER_CTAS, nullptr, nullptr };                      // 1256
    P.p[1] = { proj8 + 1024, w1b, b1, St, 20000, 256, 157,
               GATHER_CTAS + 1256, rowlist + 0 * NROWS, cnt + 0 };   // 1256
    P.p[2] = { proj8 + 1344, w3b, b3, St, 67735, 64, 530,
               GATHER_CTAS + 2512, rowlist + 2 * NROWS, cnt + 2 };   // 4240
    P.p[3] = { proj8 + 1280, w2b, b2, St, 160000, 64, 1250,
               GATHER_CTAS + 6752, rowlist + 1 * NROWS, cnt + 1 };   // 10000
    P.w0 = w0; P.b0 = b0; P.w1 = w1; P.b1 = b1;
    P.w2 = w2; P.b2 = b2; P.w3 = w3; P.b3 = b3;
    P.target = target;
    fp8_sumexp_multi<<<GATHER_CTAS + 16752, 256, DSMEM>>>(P);

    // 4) combine
    combine_kernel<<<(N + 255) / 256, 256>>>(out, N);
}